// round 8
// baseline (speedup 1.0000x reference)
#include <cuda_runtime.h>
#include <cuda_bf16.h>
#include <cstdint>

#define N_NODES 50000
#define E_MAX   625000
#define DIM     128

// ---------------------------------------------------------------------------
// Static device scratch (no runtime allocation)
// ---------------------------------------------------------------------------
__device__ int   g_cnt[N_NODES];
__device__ int   g_row[N_NODES + 1];
__device__ int   g_cur[N_NODES];
__device__ int   g_bsum[256];
__device__ int   g_bofs[256];
__device__ int   g_esrc[E_MAX];
__device__ float g_ew[E_MAX];
__device__ float g_h1[(size_t)N_NODES * DIM];
__device__ float g_hn[(size_t)N_NODES * DIM];

#define SCAN_BLK 256
#define SCAN_NB  ((N_NODES + SCAN_BLK - 1) / SCAN_BLK)   // 196

// ---------------------------------------------------------------------------
__global__ void zero_kernel(float4* __restrict__ p, int n4) {
    int i = blockIdx.x * blockDim.x + threadIdx.x;
    float4 z = make_float4(0.f, 0.f, 0.f, 0.f);
    for (; i < n4; i += gridDim.x * blockDim.x) p[i] = z;
}

__global__ void hist_kernel(const int* __restrict__ dst, int* __restrict__ cnt, int E) {
    int i = blockIdx.x * blockDim.x + threadIdx.x;
    for (; i < E; i += gridDim.x * blockDim.x)
        atomicAdd(&cnt[dst[i]], 1);
}

__global__ void scan_bsum_kernel(const int* __restrict__ cnt, int* __restrict__ bsum) {
    __shared__ int sh[SCAN_BLK];
    int i = blockIdx.x * SCAN_BLK + threadIdx.x;
    int v = (i < N_NODES) ? cnt[i] : 0;
    sh[threadIdx.x] = v;
    __syncthreads();
    for (int off = SCAN_BLK / 2; off > 0; off >>= 1) {
        if (threadIdx.x < off) sh[threadIdx.x] += sh[threadIdx.x + off];
        __syncthreads();
    }
    if (threadIdx.x == 0) bsum[blockIdx.x] = sh[0];
}

__global__ void scan_bofs_kernel(const int* __restrict__ bsum,
                                 int* __restrict__ bofs,
                                 int* __restrict__ row) {
    __shared__ int sh[SCAN_BLK];
    int t = threadIdx.x;
    int v = (t < SCAN_NB) ? bsum[t] : 0;
    sh[t] = v;
    __syncthreads();
    for (int off = 1; off < SCAN_BLK; off <<= 1) {
        int u = 0;
        if (t >= off) u = sh[t - off];
        __syncthreads();
        if (t >= off) sh[t] += u;
        __syncthreads();
    }
    if (t < SCAN_NB) bofs[t] = sh[t] - v;
    if (t == SCAN_BLK - 1) row[N_NODES] = sh[t];
}

__global__ void scan_write_kernel(const int* __restrict__ cnt,
                                  const int* __restrict__ bofs,
                                  int* __restrict__ row,
                                  int* __restrict__ cur) {
    __shared__ int sh[SCAN_BLK];
    int t = threadIdx.x;
    int i = blockIdx.x * SCAN_BLK + t;
    int v = (i < N_NODES) ? cnt[i] : 0;
    sh[t] = v;
    __syncthreads();
    for (int off = 1; off < SCAN_BLK; off <<= 1) {
        int u = 0;
        if (t >= off) u = sh[t - off];
        __syncthreads();
        if (t >= off) sh[t] += u;
        __syncthreads();
    }
    if (i < N_NODES) {
        int r = bofs[blockIdx.x] + sh[t] - v;
        row[i] = r;
        cur[i] = r;
    }
}

__global__ void scatter_kernel(const int*   __restrict__ src,
                               const int*   __restrict__ dst,
                               const float* __restrict__ wt,
                               int*   __restrict__ cur,
                               int*   __restrict__ esrc,
                               float* __restrict__ ew,
                               int E)
{
    int i = blockIdx.x * blockDim.x + threadIdx.x;
    for (; i < E; i += gridDim.x * blockDim.x) {
        int p = atomicAdd(&cur[dst[i]], 1);
        esrc[p] = src[i];
        ew[p]   = wt[i];
    }
}

// ---------------------------------------------------------------------------
// Gather v3: one warp per destination node; shfl-broadcast edge batch, MLP=8.
// ---------------------------------------------------------------------------
__global__ void gather_kernel(const float* __restrict__ h,
                              const int*   __restrict__ row,
                              const int*   __restrict__ esrc,
                              const float* __restrict__ ew,
                              float*       __restrict__ hn)
{
    int warp = (blockIdx.x * blockDim.x + threadIdx.x) >> 5;
    int lane = threadIdx.x & 31;
    if (warp >= N_NODES) return;

    int rs = row[warp];
    int re = row[warp + 1];

    float4 acc = make_float4(0.f, 0.f, 0.f, 0.f);

    for (int base = rs; base < re; base += 32) {
        int cnt = re - base; if (cnt > 32) cnt = 32;
        int   s_l = 0; float w_l = 0.f;
        if (lane < cnt) { s_l = esrc[base + lane]; w_l = ew[base + lane]; }

        for (int j = 0; j < cnt; j += 8) {
            int valid = cnt - j; if (valid > 8) valid = 8;
            float4 v[8]; float wj[8];
#pragma unroll
            for (int u = 0; u < 8; u++) {
                int   s = __shfl_sync(0xffffffffu, s_l, j + u);
                float w = __shfl_sync(0xffffffffu, w_l, j + u);
                if (u < valid) {
                    v[u]  = *(const float4*)(h + (size_t)s * DIM + lane * 4);
                    wj[u] = w;
                }
            }
#pragma unroll
            for (int u = 0; u < 8; u++) {
                if (u < valid) {
                    acc.x += wj[u] * v[u].x;
                    acc.y += wj[u] * v[u].y;
                    acc.z += wj[u] * v[u].z;
                    acc.w += wj[u] * v[u].w;
                }
            }
        }
    }

    float inv = 1.0f / fmaxf((float)(re - rs), 1.0f);
    acc.x *= inv; acc.y *= inv; acc.z *= inv; acc.w *= inv;
    *(float4*)(hn + (size_t)warp * DIM + lane * 4) = acc;
}

// ---------------------------------------------------------------------------
// SAGE GEMM v7: mma.sync bf16 split-precision with register-staged pipeline.
//   out[r, j] = sum_k h[r,k]*Ws[j,k] + hn[r,k]*Wn[j,k] + b[j]
// CTA: 128x128 tile, 256 threads = 8 warps (4m x 2n); warp tile 32x64.
// K = 256 in 8 chunks of 32. Pipeline per chunk:
//   STS(c) -> sync -> LDG(c+1) into regs -> MMA(c) -> sync
// so chunk c+1's global-load latency hides under chunk c's HMMA phase.
// Split math: A=hi+lo, W=hi+lo; keep hi*hi + hi*lo + lo*hi (drop lo*lo).
// ---------------------------------------------------------------------------
#define MM_TILE 128
#define STR 40   // smem row stride in bf16 elems (80B: 16B-aligned, conflict-free ldmatrix)

__device__ __forceinline__ void ldm4(uint32_t (&r)[4], uint32_t addr) {
    asm volatile("ldmatrix.sync.aligned.m8n8.x4.shared.b16 {%0,%1,%2,%3}, [%4];"
                 : "=r"(r[0]), "=r"(r[1]), "=r"(r[2]), "=r"(r[3]) : "r"(addr));
}
__device__ __forceinline__ void mma_bf16(float (&c)[4], const uint32_t (&a)[4],
                                         uint32_t b0, uint32_t b1) {
    asm volatile("mma.sync.aligned.m16n8k16.row.col.f32.bf16.bf16.f32 "
                 "{%0,%1,%2,%3}, {%4,%5,%6,%7}, {%8,%9}, {%0,%1,%2,%3};"
                 : "+f"(c[0]), "+f"(c[1]), "+f"(c[2]), "+f"(c[3])
                 : "r"(a[0]), "r"(a[1]), "r"(a[2]), "r"(a[3]), "r"(b0), "r"(b1));
}
__device__ __forceinline__ uint32_t smem_u32(const void* p) {
    uint32_t a;
    asm("{ .reg .u64 t; cvta.to.shared.u64 t, %1; cvt.u32.u64 %0, t; }" : "=r"(a) : "l"(p));
    return a;
}
__device__ __forceinline__ uint32_t packbf(float a, float b) {
    __nv_bfloat162 t = __floats2bfloat162_rn(a, b);
    return *(uint32_t*)&t;
}
__device__ __forceinline__ void split2(float x, float y, uint32_t& hi, uint32_t& lo) {
    float hx = __bfloat162float(__float2bfloat16_rn(x));
    float hy = __bfloat162float(__float2bfloat16_rn(y));
    hi = packbf(hx, hy);
    lo = packbf(x - hx, y - hy);
}

__global__ void sage_gemm_mma(const float* __restrict__ Aself,
                              const float* __restrict__ Aneigh,  // already deg-scaled
                              const float* __restrict__ Ws,
                              const float* __restrict__ Wn,
                              const float* __restrict__ bias,
                              float*       __restrict__ out,
                              int nrows, int do_relu)
{
    __shared__ __align__(16) unsigned short Ah[MM_TILE * STR];
    __shared__ __align__(16) unsigned short Al[MM_TILE * STR];
    __shared__ __align__(16) unsigned short Bh[MM_TILE * STR];
    __shared__ __align__(16) unsigned short Bl[MM_TILE * STR];
    __shared__ float bs[DIM];

    int tid  = threadIdx.x;
    int wid  = tid >> 5;
    int lane = tid & 31;
    int warp_m = (wid & 3) * 32;
    int warp_n = (wid >> 2) * 64;
    int rowbase = blockIdx.x * MM_TILE;

    if (tid < DIM) bs[tid] = bias[tid];

    float acc[2][8][4];
#pragma unroll
    for (int mt = 0; mt < 2; mt++)
#pragma unroll
        for (int nt = 0; nt < 8; nt++)
#pragma unroll
            for (int e = 0; e < 4; e++) acc[mt][nt][e] = 0.f;

    uint32_t ah_base = smem_u32(Ah), al_base = smem_u32(Al);
    uint32_t bh_base = smem_u32(Bh), bl_base = smem_u32(Bl);

    // ldmatrix lane address components
    int a_r = lane & 15;
    int a_c = (lane >> 4) << 3;
    int b_g = lane >> 3;
    int b_r = lane & 7;
    int b_nofs = ((b_g >> 1) << 3) + b_r;
    int b_kofs = (b_g & 1) << 3;

    // Per-thread staging addresses: thread covers A rows ar0/ar1 (2 float4 each)
    // it*256+tid, it=0..3 -> rows (it*256+tid)>>3, quad (it*256+tid)&7.
    // it and it+2 give same row parity pattern: rows r0 = tid>>3, r0+32, r0+64, r0+96; quad q = tid&7.
    int srow = tid >> 3;           // 0..31
    int sq   = tid & 7;            // 0..7

    float4 rA[4], rW[4];

    // ---- prologue: load chunk 0 ----
    {
        const float* As = Aself; const float* W = Ws; int kb = 0;
#pragma unroll
        for (int it = 0; it < 4; it++) {
            int r = srow + it * 32;
            int gr = rowbase + r; if (gr > nrows - 1) gr = nrows - 1;
            rA[it] = *(const float4*)(As + (size_t)gr * DIM + kb + sq * 4);
            rW[it] = *(const float4*)(W  + (size_t)r  * DIM + kb + sq * 4);
        }
    }

    for (int chunk = 0; chunk < 8; chunk++) {
        // ---- convert staged regs -> smem ----
#pragma unroll
        for (int it = 0; it < 4; it++) {
            int r = srow + it * 32;
            uint32_t h0, l0, h1, l1;
            split2(rA[it].x, rA[it].y, h0, l0);
            split2(rA[it].z, rA[it].w, h1, l1);
            uint32_t* ph = (uint32_t*)&Ah[r * STR + sq * 4];
            uint32_t* pl = (uint32_t*)&Al[r * STR + sq * 4];
            ph[0] = h0; ph[1] = h1;
            pl[0] = l0; pl[1] = l1;
            split2(rW[it].x, rW[it].y, h0, l0);
            split2(rW[it].z, rW[it].w, h1, l1);
            ph = (uint32_t*)&Bh[r * STR + sq * 4];
            pl = (uint32_t*)&Bl[r * STR + sq * 4];
            ph[0] = h0; ph[1] = h1;
            pl[0] = l0; pl[1] = l1;
        }
        __syncthreads();

        // ---- issue next chunk's global loads (latency hides under MMA) ----
        if (chunk < 7) {
            int nc = chunk + 1;
            const float* As; const float* W; int kb = (nc & 3) * 32;
            if (nc < 4) { As = Aself;  W = Ws; }
            else        { As = Aneigh; W = Wn; }
#pragma unroll
            for (int it = 0; it < 4; it++) {
                int r = srow + it * 32;
                int gr = rowbase + r; if (gr > nrows - 1) gr = nrows - 1;
                rA[it] = *(const float4*)(As + (size_t)gr * DIM + kb + sq * 4);
                rW[it] = *(const float4*)(W  + (size_t)r  * DIM + kb + sq * 4);
            }
        }

        // ---- MMA: 2 k-steps of 16 ----
#pragma unroll
        for (int ks = 0; ks < 2; ks++) {
            int k0 = ks * 16;

            uint32_t ahi[2][4], alo[2][4];
#pragma unroll
            for (int mt = 0; mt < 2; mt++) {
                uint32_t off = (uint32_t)((warp_m + mt * 16 + a_r) * STR + k0 + a_c) * 2;
                ldm4(ahi[mt], ah_base + off);
                ldm4(alo[mt], al_base + off);
            }

#pragma unroll
            for (int h = 0; h < 2; h++) {
                uint32_t bhi[2][4], blo[2][4];
#pragma unroll
                for (int p = 0; p < 2; p++) {
                    int n0 = warp_n + h * 32 + p * 16;
                    uint32_t off = (uint32_t)((n0 + b_nofs) * STR + k0 + b_kofs) * 2;
                    ldm4(bhi[p], bh_base + off);
                    ldm4(blo[p], bl_base + off);
                }
#pragma unroll
                for (int mt = 0; mt < 2; mt++) {
#pragma unroll
                    for (int p = 0; p < 2; p++) {
#pragma unroll
                        for (int s = 0; s < 2; s++) {
                            int nt = h * 4 + p * 2 + s;
                            mma_bf16(acc[mt][nt], ahi[mt], bhi[p][s * 2], bhi[p][s * 2 + 1]);
                            mma_bf16(acc[mt][nt], ahi[mt], blo[p][s * 2], blo[p][s * 2 + 1]);
                            mma_bf16(acc[mt][nt], alo[mt], bhi[p][s * 2], bhi[p][s * 2 + 1]);
                        }
                    }
                }
            }
        }
        __syncthreads();   // MMA reads done before next STS overwrites
    }

    // ---- epilogue: bias (+relu), float2 stores ----
    int c_r = lane >> 2;
    int c_c = (lane & 3) * 2;
#pragma unroll
    for (int mt = 0; mt < 2; mt++) {
        int r0 = rowbase + warp_m + mt * 16 + c_r;
        int r1 = r0 + 8;
#pragma unroll
        for (int nt = 0; nt < 8; nt++) {
            int c = warp_n + nt * 8 + c_c;
            float v0 = acc[mt][nt][0] + bs[c];
            float v1 = acc[mt][nt][1] + bs[c + 1];
            float v2 = acc[mt][nt][2] + bs[c];
            float v3 = acc[mt][nt][3] + bs[c + 1];
            if (do_relu) {
                v0 = fmaxf(v0, 0.f); v1 = fmaxf(v1, 0.f);
                v2 = fmaxf(v2, 0.f); v3 = fmaxf(v3, 0.f);
            }
            if (r0 < nrows) *(float2*)(out + (size_t)r0 * DIM + c) = make_float2(v0, v1);
            if (r1 < nrows) *(float2*)(out + (size_t)r1 * DIM + c) = make_float2(v2, v3);
        }
    }
}

// ---------------------------------------------------------------------------
extern "C" void kernel_launch(void* const* d_in, const int* in_sizes, int n_in,
                              void* d_out, int out_size)
{
    const float* x   = (const float*)d_in[0];
    const int*   src = (const int*)  d_in[1];
    const int*   dst = (const int*)  d_in[2];
    const float* wt  = (const float*)d_in[3];
    const float* Ws1 = (const float*)d_in[4];
    const float* Wn1 = (const float*)d_in[5];
    const float* b1  = (const float*)d_in[6];
    const float* Ws2 = (const float*)d_in[7];
    const float* Wn2 = (const float*)d_in[8];
    const float* b2  = (const float*)d_in[9];
    float* out = (float*)d_out;

    int E = in_sizes[1];

    int   *cnt, *row, *cur, *bsum, *bofs, *esrc;
    float *ew, *h1, *hn;
    cudaGetSymbolAddress((void**)&cnt,  g_cnt);
    cudaGetSymbolAddress((void**)&row,  g_row);
    cudaGetSymbolAddress((void**)&cur,  g_cur);
    cudaGetSymbolAddress((void**)&bsum, g_bsum);
    cudaGetSymbolAddress((void**)&bofs, g_bofs);
    cudaGetSymbolAddress((void**)&esrc, g_esrc);
    cudaGetSymbolAddress((void**)&ew,   g_ew);
    cudaGetSymbolAddress((void**)&h1,   g_h1);
    cudaGetSymbolAddress((void**)&hn,   g_hn);

    int eblocks  = (E + 255) / 256;
    int gblocks  = (N_NODES + MM_TILE - 1) / MM_TILE;   // 391
    int nwblocks = (N_NODES + 7) / 8;

    // ---- CSR build (by dst) ----
    zero_kernel<<<64, 256>>>((float4*)cnt, N_NODES / 4);
    hist_kernel<<<eblocks, 256>>>(dst, cnt, E);
    scan_bsum_kernel<<<SCAN_NB, SCAN_BLK>>>(cnt, bsum);
    scan_bofs_kernel<<<1, SCAN_BLK>>>(bsum, bofs, row);
    scan_write_kernel<<<SCAN_NB, SCAN_BLK>>>(cnt, bofs, row, cur);
    scatter_kernel<<<eblocks, 256>>>(src, dst, wt, cur, esrc, ew, E);

    // ---- layer 1 ----
    gather_kernel<<<nwblocks, 256>>>(x, row, esrc, ew, hn);
    sage_gemm_mma<<<gblocks, 256>>>(x, hn, Ws1, Wn1, b1, h1, N_NODES, 1);

    // ---- layer 2 ----
    gather_kernel<<<nwblocks, 256>>>(h1, row, esrc, ew, hn);
    sage_gemm_mma<<<gblocks, 256>>>(h1, hn, Ws2, Wn2, b2, out, N_NODES, 0);
}